// round 7
// baseline (speedup 1.0000x reference)
#include <cuda_runtime.h>
#include <cuda_bf16.h>
#include <mma.h>
#include <math.h>

using namespace nvcuda;

// Problem constants
constexpr int Bc   = 2;
constexpr int Tc   = 2048;
constexpr int Dc   = 2048;
constexpr int Hc   = 32;
constexpr int HKVc = 8;
constexpr int DHc  = 64;
constexpr int BT   = Bc * Tc;          // 4096
constexpr int DKV  = HKVc * DHc;       // 512

// ---------------- scratch (__device__ globals, no allocation) ----------------
// NOTE: only ever referenced from DEVICE code (never passed from host).
__device__ float g_qraw[BT * Dc];
__device__ float g_kraw[BT * DKV];
__device__ float g_vraw[BT * DKV];
__device__ float g_q  [BT * Dc];       // [B,H,T,DH] with RoPE
__device__ float g_k  [BT * DKV];      // [B,HKV,T,DH] with RoPE
__device__ float g_ctx[BT * Dc];       // [B,T,H*DH]

// ---------------- helpers -----------------------------------------------------
__device__ __forceinline__ void split4(const float4 v,
                                       __nv_bfloat16* hi, __nv_bfloat16* lo) {
    const __nv_bfloat16 hx = __float2bfloat16_rn(v.x);
    const __nv_bfloat16 hy = __float2bfloat16_rn(v.y);
    const __nv_bfloat16 hz = __float2bfloat16_rn(v.z);
    const __nv_bfloat16 hw = __float2bfloat16_rn(v.w);
    __nv_bfloat162* h2 = reinterpret_cast<__nv_bfloat162*>(hi);
    __nv_bfloat162* l2 = reinterpret_cast<__nv_bfloat162*>(lo);
    h2[0] = __halves2bfloat162(hx, hy);
    h2[1] = __halves2bfloat162(hz, hw);
    l2[0] = __halves2bfloat162(__float2bfloat16_rn(v.x - __bfloat162float(hx)),
                               __float2bfloat16_rn(v.y - __bfloat162float(hy)));
    l2[1] = __halves2bfloat162(__float2bfloat16_rn(v.z - __bfloat162float(hz)),
                               __float2bfloat16_rn(v.w - __bfloat162float(hw)));
}

// ---------------- bf16x3 split GEMM via wmma (device body) -------------------
// C[4096, N] = A[4096, 2048] @ B[2048, N], all fp32 row-major.
// block = 256 (8 warps: 4 along M x 2 along N), CTA tile 128x128, BK=32.
template <int N>
__device__ __forceinline__ void mma_gemm_body(const float* __restrict__ A,
                                              const float* __restrict__ B,
                                              float* __restrict__ C) {
    constexpr int K  = 2048;
    constexpr int BM = 128, BN = 128, BK = 32;
    constexpr int ASTR = BK + 8;   // 40 bf16 = 80 B per row
    constexpr int BSTR = BN + 8;   // 136 bf16 = 272 B per row

    __shared__ __align__(32) __nv_bfloat16 Ah[BM][ASTR];
    __shared__ __align__(32) __nv_bfloat16 Al[BM][ASTR];
    __shared__ __align__(32) __nv_bfloat16 Bh[BK][BSTR];
    __shared__ __align__(32) __nv_bfloat16 Bl[BK][BSTR];

    const int tid  = threadIdx.x;
    const int warp = tid >> 5;
    const int wm   = (warp >> 1) * 32;   // warp row origin in tile
    const int wn   = (warp & 1) * 64;    // warp col origin in tile
    const int brow = blockIdx.y * BM;
    const int bcol = blockIdx.x * BN;

    const int ar = tid >> 3;             // 0..31 (A row, step 32)
    const int ac = (tid & 7) * 4;        // 0..28 (A col)
    const int bk = tid >> 5;             // 0..7  (B k-row, step 8)
    const int bn = (tid & 31) * 4;       // 0..124 (B col)

    wmma::fragment<wmma::accumulator, 16, 16, 16, float> acc[2][4];
#pragma unroll
    for (int mi = 0; mi < 2; mi++) {
#pragma unroll
        for (int nj = 0; nj < 4; nj++) {
            wmma::fill_fragment(acc[mi][nj], 0.0f);
        }
    }

    float4 aReg[4];
    float4 bReg[4];
#pragma unroll
    for (int i = 0; i < 4; i++) {
        aReg[i] = *reinterpret_cast<const float4*>(A + (size_t)(brow + ar + i * 32) * K + ac);
        bReg[i] = *reinterpret_cast<const float4*>(B + (size_t)(bk + i * 8) * N + bcol + bn);
    }

    for (int kt = 0; kt < K / BK; kt++) {
#pragma unroll
        for (int i = 0; i < 4; i++) {
            const int r = ar + i * 32;
            split4(aReg[i], &Ah[r][ac], &Al[r][ac]);
            const int rb = bk + i * 8;
            split4(bReg[i], &Bh[rb][bn], &Bl[rb][bn]);
        }
        __syncthreads();

        if (kt + 1 < K / BK) {
            const int k0 = (kt + 1) * BK;
#pragma unroll
            for (int i = 0; i < 4; i++) {
                aReg[i] = *reinterpret_cast<const float4*>(
                    A + (size_t)(brow + ar + i * 32) * K + k0 + ac);
                bReg[i] = *reinterpret_cast<const float4*>(
                    B + (size_t)(k0 + bk + i * 8) * N + bcol + bn);
            }
        }

#pragma unroll
        for (int ks = 0; ks < 2; ks++) {
            wmma::fragment<wmma::matrix_a, 16, 16, 16, __nv_bfloat16, wmma::row_major> fAh[2];
            wmma::fragment<wmma::matrix_a, 16, 16, 16, __nv_bfloat16, wmma::row_major> fAl[2];
#pragma unroll
            for (int mi = 0; mi < 2; mi++) {
                wmma::load_matrix_sync(fAh[mi], &Ah[wm + mi * 16][ks * 16], ASTR);
                wmma::load_matrix_sync(fAl[mi], &Al[wm + mi * 16][ks * 16], ASTR);
            }
#pragma unroll
            for (int nj = 0; nj < 4; nj++) {
                wmma::fragment<wmma::matrix_b, 16, 16, 16, __nv_bfloat16, wmma::row_major> fBh;
                wmma::fragment<wmma::matrix_b, 16, 16, 16, __nv_bfloat16, wmma::row_major> fBl;
                wmma::load_matrix_sync(fBh, &Bh[ks * 16][wn + nj * 16], BSTR);
                wmma::load_matrix_sync(fBl, &Bl[ks * 16][wn + nj * 16], BSTR);
#pragma unroll
                for (int mi = 0; mi < 2; mi++) {
                    wmma::mma_sync(acc[mi][nj], fAh[mi], fBh, acc[mi][nj]);
                    wmma::mma_sync(acc[mi][nj], fAh[mi], fBl, acc[mi][nj]);
                    wmma::mma_sync(acc[mi][nj], fAl[mi], fBh, acc[mi][nj]);
                }
            }
        }
        __syncthreads();
    }

#pragma unroll
    for (int mi = 0; mi < 2; mi++) {
#pragma unroll
        for (int nj = 0; nj < 4; nj++) {
            float* p = C + (size_t)(brow + wm + mi * 16) * N + bcol + wn + nj * 16;
            wmma::store_matrix_sync(p, acc[mi][nj], N, wmma::mem_row_major);
        }
    }
}

// Wrappers: scratch globals referenced from DEVICE code only.
__global__ __launch_bounds__(256) void k_qproj(const float* __restrict__ x,
                                               const float* __restrict__ W) {
    mma_gemm_body<Dc>(x, W, g_qraw);
}
__global__ __launch_bounds__(256) void k_kproj(const float* __restrict__ x,
                                               const float* __restrict__ W) {
    mma_gemm_body<DKV>(x, W, g_kraw);
}
__global__ __launch_bounds__(256) void k_vproj(const float* __restrict__ x,
                                               const float* __restrict__ W) {
    mma_gemm_body<DKV>(x, W, g_vraw);
}
__global__ __launch_bounds__(256) void k_oproj(const float* __restrict__ W,
                                               float* __restrict__ out) {
    mma_gemm_body<Dc>(g_ctx, W, out);
}

// ---------------- RoPE + layout transforms -----------------------------------
#define ROPE_LN_C 0.28782313662425575f

__global__ __launch_bounds__(256) void rope_q_kernel() {
    const int idx = blockIdx.x * 256 + threadIdx.x;   // over [B,H,T,DH]
    const int d = idx & 63;
    const int t = (idx >> 6) & 2047;
    const int h = (idx >> 17) & 31;
    const int b = idx >> 22;
    const size_t row = (size_t)(b * Tc + t) * Dc + h * DHc;
    const float raw  = g_qraw[row + d];
    const float pair = g_qraw[row + ((d < 32) ? d + 32 : d - 32)];
    const float rot  = (d < 32) ? -pair : pair;
    const int   i    = d & 31;
    const float invf = expf(-(float)i * ROPE_LN_C);
    const float ang  = (float)t * invf;
    g_q[idx] = raw * cosf(ang) + rot * sinf(ang);
}

__global__ __launch_bounds__(256) void rope_k_kernel() {
    const int idx = blockIdx.x * 256 + threadIdx.x;   // over [B,HKV,T,DH]
    const int d  = idx & 63;
    const int t  = (idx >> 6) & 2047;
    const int kv = (idx >> 17) & 7;
    const int b  = idx >> 20;
    const size_t row = (size_t)(b * Tc + t) * DKV + kv * DHc;
    const float raw  = g_kraw[row + d];
    const float pair = g_kraw[row + ((d < 32) ? d + 32 : d - 32)];
    const float rot  = (d < 32) ? -pair : pair;
    const int   i    = d & 31;
    const float invf = expf(-(float)i * ROPE_LN_C);
    const float ang  = (float)t * invf;
    g_k[idx] = raw * cosf(ang) + rot * sinf(ang);
}

// ---------------- Causal flash attention (bf16x3 wmma, fp32 softmax) ---------
// grid: (T/64, H, B), block: 256 (8 warps: 4 along q x 2 along key/dh)
__global__ __launch_bounds__(256) void attn_kernel() {
    constexpr int BQ  = 64;
    constexpr int BKT = 32;
    constexpr int KP  = 72;   // bf16 row stride for K/V/Q-staging
    constexpr int PP  = 40;   // bf16 row stride for P
    constexpr int OP  = 72;   // fp32 row stride for Ss/Os

    __shared__ __align__(32) __nv_bfloat16 Kh[BKT][KP];
    __shared__ __align__(32) __nv_bfloat16 Kl[BKT][KP];
    __shared__ __align__(32) __nv_bfloat16 Vh[BKT][KP];
    __shared__ __align__(32) __nv_bfloat16 Vl[BKT][KP];
    __shared__ __align__(32) __nv_bfloat16 Ph[BQ][PP];
    __shared__ __align__(32) __nv_bfloat16 Pl[BQ][PP];
    __shared__ __align__(32) float SsOs[BQ][OP];   // S tile, O tile, Q staging
    __shared__ float m_s[BQ], l_s[BQ], corr_s[BQ];

    const int tid  = threadIdx.x;
    const int warp = tid >> 5;
    const int wr   = warp >> 1;    // 0..3: 16-row group of q
    const int wc   = warp & 1;     // 0..1: 16-col group (S) / 32-col group (O)
    const int qt   = blockIdx.x;
    const int h    = blockIdx.y;
    const int b    = blockIdx.z;
    const int kv   = h >> 2;

    const float* Qp = g_q + ((size_t)(b * Hc + h) * Tc + qt * BQ) * DHc;
    const float* Kp = g_k + (size_t)(b * HKVc + kv) * Tc * DHc;

    // ---- stage Q (64x64 fp32) into SsOs as bf16 hi/lo, then load fragments --
    __nv_bfloat16* Qh = reinterpret_cast<__nv_bfloat16*>(&SsOs[0][0]);
    __nv_bfloat16* Ql = Qh + BQ * KP;   // 9216 B + 9216 B = 18432 B = sizeof(SsOs)
    for (int i = tid; i < BQ * DHc / 4; i += 256) {
        const int r = i >> 4;
        const int c = (i & 15) << 2;
        const float4 v = *reinterpret_cast<const float4*>(Qp + r * DHc + c);
        split4(v, Qh + r * KP + c, Ql + r * KP + c);
    }
    if (tid < BQ) { m_s[tid] = -1e30f; l_s[tid] = 0.f; }
    __syncthreads();

    wmma::fragment<wmma::matrix_a, 16, 16, 16, __nv_bfloat16, wmma::row_major> fQh[4];
    wmma::fragment<wmma::matrix_a, 16, 16, 16, __nv_bfloat16, wmma::row_major> fQl[4];
#pragma unroll
    for (int kd = 0; kd < 4; kd++) {
        wmma::load_matrix_sync(fQh[kd], Qh + (wr * 16) * KP + kd * 16, KP);
        wmma::load_matrix_sync(fQl[kd], Ql + (wr * 16) * KP + kd * 16, KP);
    }

    float o[4][4];
#pragma unroll
    for (int i = 0; i < 4; i++) {
#pragma unroll
        for (int j = 0; j < 4; j++) { o[i][j] = 0.f; }
    }
    const int qr0 = (tid >> 4) * 4;
    const int dc0 = (tid & 15) * 4;
    const int ntiles = 2 * qt + 2;

    for (int kt = 0; kt < ntiles; kt++) {
        const int kbase = kt * BKT;

        // ---- 1. load K (roped) and V (raw layout) tiles, split to bf16 ------
        for (int i = tid; i < BKT * DHc / 4; i += 256) {
            const int r = i >> 4;
            const int c = (i & 15) << 2;
            const float4 kvec = *reinterpret_cast<const float4*>(
                Kp + (size_t)(kbase + r) * DHc + c);
            split4(kvec, &Kh[r][c], &Kl[r][c]);
            const float4 vvec = *reinterpret_cast<const float4*>(
                g_vraw + (size_t)(b * Tc + kbase + r) * DKV + kv * DHc + c);
            split4(vvec, &Vh[r][c], &Vl[r][c]);
        }
        __syncthreads();

        // ---- 2. S = Q K^T (bf16x3), each warp a 16x16 block ------------------
        {
            wmma::fragment<wmma::accumulator, 16, 16, 16, float> accS;
            wmma::fill_fragment(accS, 0.0f);
#pragma unroll
            for (int kd = 0; kd < 4; kd++) {
                wmma::fragment<wmma::matrix_b, 16, 16, 16, __nv_bfloat16, wmma::col_major> fKh;
                wmma::fragment<wmma::matrix_b, 16, 16, 16, __nv_bfloat16, wmma::col_major> fKl;
                wmma::load_matrix_sync(fKh, &Kh[wc * 16][kd * 16], KP);
                wmma::load_matrix_sync(fKl, &Kl[wc * 16][kd * 16], KP);
                wmma::mma_sync(accS, fQh[kd], fKh, accS);
                wmma::mma_sync(accS, fQh[kd], fKl, accS);
                wmma::mma_sync(accS, fQl[kd], fKh, accS);
            }
            wmma::store_matrix_sync(&SsOs[wr * 16][wc * 16], accS, OP, wmma::mem_row_major);
        }
        __syncthreads();

        // ---- 3. online softmax (thread-per-row), write P hi/lo --------------
        if (tid < BQ) {
            const int r  = tid;
            const int qi = qt * BQ + r;
            const float mold = m_s[r];
            float mmax = mold;
#pragma unroll
            for (int c = 0; c < BKT; c++) {
                const float s = (kbase + c <= qi) ? SsOs[r][c] * 0.125f : -1e30f;
                mmax = fmaxf(mmax, s);
            }
            const float cr = __expf(mold - mmax);
            float lsum = 0.f;
#pragma unroll
            for (int c = 0; c < BKT; c++) {
                const float s = (kbase + c <= qi) ? SsOs[r][c] * 0.125f : -1e30f;
                const float e = __expf(s - mmax);
                lsum += e;
                const __nv_bfloat16 eh = __float2bfloat16_rn(e);
                Ph[r][c] = eh;
                Pl[r][c] = __float2bfloat16_rn(e - __bfloat162float(eh));
            }
            m_s[r]    = mmax;
            l_s[r]    = l_s[r] * cr + lsum;
            corr_s[r] = cr;
        }
        __syncthreads();

        // ---- 4. O_tile = P V (bf16x3), each warp 16x32 -----------------------
        {
            wmma::fragment<wmma::accumulator, 16, 16, 16, float> accO[2];
            wmma::fill_fragment(accO[0], 0.0f);
            wmma::fill_fragment(accO[1], 0.0f);
#pragma unroll
            for (int ks = 0; ks < 2; ks++) {
                wmma::fragment<wmma::matrix_a, 16, 16, 16, __nv_bfloat16, wmma::row_major> fPh;
                wmma::fragment<wmma::matrix_a, 16, 16, 16, __nv_bfloat16, wmma::row_major> fPl;
                wmma::load_matrix_sync(fPh, &Ph[wr * 16][ks * 16], PP);
                wmma::load_matrix_sync(fPl, &Pl[wr * 16][ks * 16], PP);
#pragma unroll
                for (int nj = 0; nj < 2; nj++) {
                    wmma::fragment<wmma::matrix_b, 16, 16, 16, __nv_bfloat16, wmma::row_major> fVh;
                    wmma::fragment<wmma::matrix_b, 16, 16, 16, __nv_bfloat16, wmma::row_major> fVl;
                    wmma::load_matrix_sync(fVh, &Vh[ks * 16][wc * 32 + nj * 16], KP);
                    wmma::load_matrix_sync(fVl, &Vl[ks * 16][wc * 32 + nj * 16], KP);
                    wmma::mma_sync(accO[nj], fPh, fVh, accO[nj]);
                    wmma::mma_sync(accO[nj], fPh, fVl, accO[nj]);
                    wmma::mma_sync(accO[nj], fPl, fVh, accO[nj]);
                }
            }
            wmma::store_matrix_sync(&SsOs[wr * 16][wc * 32],      accO[0], OP, wmma::mem_row_major);
            wmma::store_matrix_sync(&SsOs[wr * 16][wc * 32 + 16], accO[1], OP, wmma::mem_row_major);
        }
        __syncthreads();

        // ---- 5. rescale + accumulate into register O -------------------------
#pragma unroll
        for (int i = 0; i < 4; i++) {
            const float cr = corr_s[qr0 + i];
#pragma unroll
            for (int j = 0; j < 4; j++) {
                o[i][j] = o[i][j] * cr + SsOs[qr0 + i][dc0 + j];
            }
        }
        __syncthreads();
    }

    // ---- normalize and write ctx[b][t][h*DH + d] -----------------------------
#pragma unroll
    for (int i = 0; i < 4; i++) {
        const float inv = 1.f / l_s[qr0 + i];
        const size_t off =
            (size_t)(b * Tc + qt * BQ + qr0 + i) * Dc + h * DHc + dc0;
        *reinterpret_cast<float4*>(g_ctx + off) =
            make_float4(o[i][0] * inv, o[i][1] * inv, o[i][2] * inv, o[i][3] * inv);
    }
}

// ---------------- launch ------------------------------------------------------
extern "C" void kernel_launch(void* const* d_in, const int* in_sizes, int n_in,
                              void* d_out, int out_size) {
    const float* x  = (const float*)d_in[0];
    const float* Wq = (const float*)d_in[1];
    const float* Wk = (const float*)d_in[2];
    const float* Wv = (const float*)d_in[3];
    const float* Wo = (const float*)d_in[4];
    float* out = (float*)d_out;

    dim3 gridBig(Dc / 128, BT / 128);
    dim3 gridKV(DKV / 128, BT / 128);

    k_qproj<<<gridBig, 256>>>(x, Wq);
    k_kproj<<<gridKV, 256>>>(x, Wk);
    k_vproj<<<gridKV, 256>>>(x, Wv);

    rope_q_kernel<<<(BT * Dc) / 256, 256>>>();
    rope_k_kernel<<<(BT * DKV) / 256, 256>>>();

    attn_kernel<<<dim3(Tc / 64, Hc, Bc), 256>>>();

    k_oproj<<<gridBig, 256>>>(Wo, out);
}

// round 8
// speedup vs baseline: 1.5535x; 1.5535x over previous
#include <cuda_runtime.h>
#include <cuda_bf16.h>
#include <mma.h>
#include <math.h>

using namespace nvcuda;

// Problem constants
constexpr int Bc   = 2;
constexpr int Tc   = 2048;
constexpr int Dc   = 2048;
constexpr int Hc   = 32;
constexpr int HKVc = 8;
constexpr int DHc  = 64;
constexpr int BT   = Bc * Tc;          // 4096
constexpr int DKV  = HKVc * DHc;       // 512

// ---------------- scratch (__device__ globals, no allocation) ----------------
// NOTE: only ever referenced from DEVICE code (never passed from host).
__device__ float g_qraw[BT * Dc];
__device__ float g_kraw[BT * DKV];
__device__ float g_vraw[BT * DKV];
__device__ float g_q  [BT * Dc];       // [B,H,T,DH] with RoPE
__device__ float g_k  [BT * DKV];      // [B,HKV,T,DH] with RoPE
__device__ float g_ctx[BT * Dc];       // [B,T,H*DH]

// ---------------- helpers -----------------------------------------------------
__device__ __forceinline__ void split4(const float4 v,
                                       __nv_bfloat16* hi, __nv_bfloat16* lo) {
    const __nv_bfloat16 hx = __float2bfloat16_rn(v.x);
    const __nv_bfloat16 hy = __float2bfloat16_rn(v.y);
    const __nv_bfloat16 hz = __float2bfloat16_rn(v.z);
    const __nv_bfloat16 hw = __float2bfloat16_rn(v.w);
    __nv_bfloat162* h2 = reinterpret_cast<__nv_bfloat162*>(hi);
    __nv_bfloat162* l2 = reinterpret_cast<__nv_bfloat162*>(lo);
    h2[0] = __halves2bfloat162(hx, hy);
    h2[1] = __halves2bfloat162(hz, hw);
    l2[0] = __halves2bfloat162(__float2bfloat16_rn(v.x - __bfloat162float(hx)),
                               __float2bfloat16_rn(v.y - __bfloat162float(hy)));
    l2[1] = __halves2bfloat162(__float2bfloat16_rn(v.z - __bfloat162float(hz)),
                               __float2bfloat16_rn(v.w - __bfloat162float(hw)));
}

// ---------------- bf16x3 split GEMM via wmma (device body) -------------------
// C[4096, N] = A[4096, 2048] @ B[2048, N], all fp32 row-major.
// block = 256 (8 warps: 4 along M x 2 along N), CTA tile 128x128, BK=32.
template <int N>
__device__ __forceinline__ void mma_gemm_body(const float* __restrict__ A,
                                              const float* __restrict__ B,
                                              float* __restrict__ C) {
    constexpr int K  = 2048;
    constexpr int BM = 128, BN = 128, BK = 32;
    constexpr int ASTR = BK + 8;   // 40 bf16 = 80 B per row
    constexpr int BSTR = BN + 8;   // 136 bf16 = 272 B per row

    __shared__ __align__(32) __nv_bfloat16 Ah[BM][ASTR];
    __shared__ __align__(32) __nv_bfloat16 Al[BM][ASTR];
    __shared__ __align__(32) __nv_bfloat16 Bh[BK][BSTR];
    __shared__ __align__(32) __nv_bfloat16 Bl[BK][BSTR];

    const int tid  = threadIdx.x;
    const int warp = tid >> 5;
    const int wm   = (warp >> 1) * 32;   // warp row origin in tile
    const int wn   = (warp & 1) * 64;    // warp col origin in tile
    const int brow = blockIdx.y * BM;
    const int bcol = blockIdx.x * BN;

    const int ar = tid >> 3;             // 0..31 (A row, step 32)
    const int ac = (tid & 7) * 4;        // 0..28 (A col)
    const int bk = tid >> 5;             // 0..7  (B k-row, step 8)
    const int bn = (tid & 31) * 4;       // 0..124 (B col)

    wmma::fragment<wmma::accumulator, 16, 16, 16, float> acc[2][4];
#pragma unroll
    for (int mi = 0; mi < 2; mi++) {
#pragma unroll
        for (int nj = 0; nj < 4; nj++) {
            wmma::fill_fragment(acc[mi][nj], 0.0f);
        }
    }

    float4 aReg[4];
    float4 bReg[4];
#pragma unroll
    for (int i = 0; i < 4; i++) {
        aReg[i] = *reinterpret_cast<const float4*>(A + (size_t)(brow + ar + i * 32) * K + ac);
        bReg[i] = *reinterpret_cast<const float4*>(B + (size_t)(bk + i * 8) * N + bcol + bn);
    }

    for (int kt = 0; kt < K / BK; kt++) {
#pragma unroll
        for (int i = 0; i < 4; i++) {
            const int r = ar + i * 32;
            split4(aReg[i], &Ah[r][ac], &Al[r][ac]);
            const int rb = bk + i * 8;
            split4(bReg[i], &Bh[rb][bn], &Bl[rb][bn]);
        }
        __syncthreads();

        if (kt + 1 < K / BK) {
            const int k0 = (kt + 1) * BK;
#pragma unroll
            for (int i = 0; i < 4; i++) {
                aReg[i] = *reinterpret_cast<const float4*>(
                    A + (size_t)(brow + ar + i * 32) * K + k0 + ac);
                bReg[i] = *reinterpret_cast<const float4*>(
                    B + (size_t)(k0 + bk + i * 8) * N + bcol + bn);
            }
        }

#pragma unroll
        for (int ks = 0; ks < 2; ks++) {
            wmma::fragment<wmma::matrix_a, 16, 16, 16, __nv_bfloat16, wmma::row_major> fAh[2];
            wmma::fragment<wmma::matrix_a, 16, 16, 16, __nv_bfloat16, wmma::row_major> fAl[2];
#pragma unroll
            for (int mi = 0; mi < 2; mi++) {
                wmma::load_matrix_sync(fAh[mi], &Ah[wm + mi * 16][ks * 16], ASTR);
                wmma::load_matrix_sync(fAl[mi], &Al[wm + mi * 16][ks * 16], ASTR);
            }
#pragma unroll
            for (int nj = 0; nj < 4; nj++) {
                wmma::fragment<wmma::matrix_b, 16, 16, 16, __nv_bfloat16, wmma::row_major> fBh;
                wmma::fragment<wmma::matrix_b, 16, 16, 16, __nv_bfloat16, wmma::row_major> fBl;
                wmma::load_matrix_sync(fBh, &Bh[ks * 16][wn + nj * 16], BSTR);
                wmma::load_matrix_sync(fBl, &Bl[ks * 16][wn + nj * 16], BSTR);
#pragma unroll
                for (int mi = 0; mi < 2; mi++) {
                    wmma::mma_sync(acc[mi][nj], fAh[mi], fBh, acc[mi][nj]);
                    wmma::mma_sync(acc[mi][nj], fAh[mi], fBl, acc[mi][nj]);
                    wmma::mma_sync(acc[mi][nj], fAl[mi], fBh, acc[mi][nj]);
                }
            }
        }
        __syncthreads();
    }

#pragma unroll
    for (int mi = 0; mi < 2; mi++) {
#pragma unroll
        for (int nj = 0; nj < 4; nj++) {
            float* p = C + (size_t)(brow + wm + mi * 16) * N + bcol + wn + nj * 16;
            wmma::store_matrix_sync(p, acc[mi][nj], N, wmma::mem_row_major);
        }
    }
}

// Wrappers: scratch globals referenced from DEVICE code only.
__global__ __launch_bounds__(256) void k_qproj(const float* __restrict__ x,
                                               const float* __restrict__ W) {
    mma_gemm_body<Dc>(x, W, g_qraw);
}
__global__ __launch_bounds__(256) void k_kproj(const float* __restrict__ x,
                                               const float* __restrict__ W) {
    mma_gemm_body<DKV>(x, W, g_kraw);
}
__global__ __launch_bounds__(256) void k_vproj(const float* __restrict__ x,
                                               const float* __restrict__ W) {
    mma_gemm_body<DKV>(x, W, g_vraw);
}
__global__ __launch_bounds__(256) void k_oproj(const float* __restrict__ W,
                                               float* __restrict__ out) {
    mma_gemm_body<Dc>(g_ctx, W, out);
}

// ---------------- RoPE + layout transforms -----------------------------------
#define ROPE_LN_C 0.28782313662425575f

__global__ __launch_bounds__(256) void rope_q_kernel() {
    const int idx = blockIdx.x * 256 + threadIdx.x;   // over [B,H,T,DH]
    const int d = idx & 63;
    const int t = (idx >> 6) & 2047;
    const int h = (idx >> 17) & 31;
    const int b = idx >> 22;
    const size_t row = (size_t)(b * Tc + t) * Dc + h * DHc;
    const float raw  = g_qraw[row + d];
    const float pair = g_qraw[row + ((d < 32) ? d + 32 : d - 32)];
    const float rot  = (d < 32) ? -pair : pair;
    const int   i    = d & 31;
    const float invf = expf(-(float)i * ROPE_LN_C);
    const float ang  = (float)t * invf;
    g_q[idx] = raw * cosf(ang) + rot * sinf(ang);
}

__global__ __launch_bounds__(256) void rope_k_kernel() {
    const int idx = blockIdx.x * 256 + threadIdx.x;   // over [B,HKV,T,DH]
    const int d  = idx & 63;
    const int t  = (idx >> 6) & 2047;
    const int kv = (idx >> 17) & 7;
    const int b  = idx >> 20;
    const size_t row = (size_t)(b * Tc + t) * DKV + kv * DHc;
    const float raw  = g_kraw[row + d];
    const float pair = g_kraw[row + ((d < 32) ? d + 32 : d - 32)];
    const float rot  = (d < 32) ? -pair : pair;
    const int   i    = d & 31;
    const float invf = expf(-(float)i * ROPE_LN_C);
    const float ang  = (float)t * invf;
    g_k[idx] = raw * cosf(ang) + rot * sinf(ang);
}

// ---------------- Causal flash attention (bf16x3 wmma, parallel softmax) -----
// grid: (T/64, H, B), block: 256 (8 warps: 4 along q x 2 along key/dh)
__global__ __launch_bounds__(256) void attn_kernel() {
    constexpr int BQ  = 64;
    constexpr int BKT = 32;
    constexpr int KP  = 72;   // bf16 row stride for K/V/Q-staging
    constexpr int PP  = 40;   // bf16 row stride for P
    constexpr int OP  = 72;   // fp32 row stride for Ss/Os

    __shared__ __align__(32) __nv_bfloat16 Kh[BKT][KP];
    __shared__ __align__(32) __nv_bfloat16 Kl[BKT][KP];
    __shared__ __align__(32) __nv_bfloat16 Vh[BKT][KP];
    __shared__ __align__(32) __nv_bfloat16 Vl[BKT][KP];
    __shared__ __align__(32) __nv_bfloat16 Ph[BQ][PP];
    __shared__ __align__(32) __nv_bfloat16 Pl[BQ][PP];
    __shared__ __align__(32) float SsOs[BQ][OP];   // Q staging, S tile, O tile
    __shared__ float m_s[BQ], l_s[BQ], corr_s[BQ];

    const int tid  = threadIdx.x;
    const int warp = tid >> 5;
    const int wr   = warp >> 1;    // 0..3: 16-row group of q
    const int wc   = warp & 1;     // 0..1: 16-col group (S) / 32-col group (O)
    const int qt   = blockIdx.x;
    const int h    = blockIdx.y;
    const int b    = blockIdx.z;
    const int kv   = h >> 2;

    const float* Qp = g_q + ((size_t)(b * Hc + h) * Tc + qt * BQ) * DHc;
    const float* Kp = g_k + (size_t)(b * HKVc + kv) * Tc * DHc;
    const float* Vp = g_vraw + (size_t)(b * Tc) * DKV + kv * DHc;   // [t][512] rows

    // ---- stage Q (64x64 fp32) into SsOs as bf16 hi/lo, then load fragments --
    __nv_bfloat16* Qh = reinterpret_cast<__nv_bfloat16*>(&SsOs[0][0]);
    __nv_bfloat16* Ql = Qh + BQ * KP;
    for (int i = tid; i < BQ * DHc / 4; i += 256) {
        const int r = i >> 4;
        const int c = (i & 15) << 2;
        const float4 v = *reinterpret_cast<const float4*>(Qp + r * DHc + c);
        split4(v, Qh + r * KP + c, Ql + r * KP + c);
    }
    if (tid < BQ) { m_s[tid] = -1e30f; l_s[tid] = 0.f; }
    __syncthreads();

    wmma::fragment<wmma::matrix_a, 16, 16, 16, __nv_bfloat16, wmma::row_major> fQh[4];
    wmma::fragment<wmma::matrix_a, 16, 16, 16, __nv_bfloat16, wmma::row_major> fQl[4];
#pragma unroll
    for (int kd = 0; kd < 4; kd++) {
        wmma::load_matrix_sync(fQh[kd], Qh + (wr * 16) * KP + kd * 16, KP);
        wmma::load_matrix_sync(fQl[kd], Ql + (wr * 16) * KP + kd * 16, KP);
    }
    __syncthreads();   // Q staging region is reused as S/O below

    float o[4][4];
#pragma unroll
    for (int i = 0; i < 4; i++) {
#pragma unroll
        for (int j = 0; j < 4; j++) { o[i][j] = 0.f; }
    }
    const int qr0  = (tid >> 4) * 4;   // output rows (rescale/writeback)
    const int dc0  = (tid & 15) * 4;   // output cols
    const int srow = tid >> 2;         // softmax row (4 threads per row)
    const int ssub = tid & 3;          // softmax sub-column group (8 cols)
    const int ntiles = 2 * qt + 2;

    // global-load coords for K/V tiles: 2 float4 per thread
    const int lr = tid >> 4;           // 0..15 (+16 for second)
    const int lc = (tid & 15) << 2;    // 0..60

    float4 kReg[2], vReg[2];
#pragma unroll
    for (int j = 0; j < 2; j++) {
        kReg[j] = *reinterpret_cast<const float4*>(Kp + (size_t)(lr + j * 16) * DHc + lc);
        vReg[j] = *reinterpret_cast<const float4*>(Vp + (size_t)(lr + j * 16) * DKV + lc);
    }

    for (int kt = 0; kt < ntiles; kt++) {
        const int kbase = kt * BKT;

        // ---- split-store current K/V tile --------------------------------------
#pragma unroll
        for (int j = 0; j < 2; j++) {
            const int r = lr + j * 16;
            split4(kReg[j], &Kh[r][lc], &Kl[r][lc]);
            split4(vReg[j], &Vh[r][lc], &Vl[r][lc]);
        }
        __syncthreads();   // b1

        // ---- prefetch next tile ------------------------------------------------
        if (kt + 1 < ntiles) {
            const int nbase = kbase + BKT;
#pragma unroll
            for (int j = 0; j < 2; j++) {
                kReg[j] = *reinterpret_cast<const float4*>(
                    Kp + (size_t)(nbase + lr + j * 16) * DHc + lc);
                vReg[j] = *reinterpret_cast<const float4*>(
                    Vp + (size_t)(nbase + lr + j * 16) * DKV + lc);
            }
        }

        // ---- S = Q K^T (bf16x3), each warp a 16x16 block -----------------------
        {
            wmma::fragment<wmma::accumulator, 16, 16, 16, float> accS;
            wmma::fill_fragment(accS, 0.0f);
#pragma unroll
            for (int kd = 0; kd < 4; kd++) {
                wmma::fragment<wmma::matrix_b, 16, 16, 16, __nv_bfloat16, wmma::col_major> fKh;
                wmma::fragment<wmma::matrix_b, 16, 16, 16, __nv_bfloat16, wmma::col_major> fKl;
                wmma::load_matrix_sync(fKh, &Kh[wc * 16][kd * 16], KP);
                wmma::load_matrix_sync(fKl, &Kl[wc * 16][kd * 16], KP);
                wmma::mma_sync(accS, fQh[kd], fKh, accS);
                wmma::mma_sync(accS, fQh[kd], fKl, accS);
                wmma::mma_sync(accS, fQl[kd], fKh, accS);
            }
            wmma::store_matrix_sync(&SsOs[wr * 16][wc * 16], accS, OP, wmma::mem_row_major);
        }
        __syncthreads();   // b2

        // ---- online softmax: 4 threads per row, 8 cols each --------------------
        {
            const int qi = qt * BQ + srow;
            const float mold = m_s[srow];
            float sv[8];
            float mmax = mold;
#pragma unroll
            for (int j = 0; j < 8; j++) {
                const int ccol = ssub * 8 + j;
                const float s = (kbase + ccol <= qi) ? SsOs[srow][ccol] * 0.125f : -1e30f;
                sv[j] = s;
                mmax = fmaxf(mmax, s);
            }
            mmax = fmaxf(mmax, __shfl_xor_sync(0xffffffffu, mmax, 1));
            mmax = fmaxf(mmax, __shfl_xor_sync(0xffffffffu, mmax, 2));
            float lsum = 0.f;
#pragma unroll
            for (int j = 0; j < 8; j++) {
                const float e = __expf(sv[j] - mmax);
                lsum += e;
                const __nv_bfloat16 eh = __float2bfloat16_rn(e);
                Ph[srow][ssub * 8 + j] = eh;
                Pl[srow][ssub * 8 + j] = __float2bfloat16_rn(e - __bfloat162float(eh));
            }
            lsum += __shfl_xor_sync(0xffffffffu, lsum, 1);
            lsum += __shfl_xor_sync(0xffffffffu, lsum, 2);
            if (ssub == 0) {
                const float cr = __expf(mold - mmax);
                m_s[srow]    = mmax;
                l_s[srow]    = l_s[srow] * cr + lsum;
                corr_s[srow] = cr;
            }
        }
        __syncthreads();   // b3

        // ---- O_tile = P V (bf16x3), each warp 16x32 ----------------------------
        {
            wmma::fragment<wmma::accumulator, 16, 16, 16, float> accO[2];
            wmma::fill_fragment(accO[0], 0.0f);
            wmma::fill_fragment(accO[1], 0.0f);
#pragma unroll
            for (int ks = 0; ks < 2; ks++) {
                wmma::fragment<wmma::matrix_a, 16, 16, 16, __nv_bfloat16, wmma::row_major> fPh;
                wmma::fragment<wmma::matrix_a, 16, 16, 16, __nv_bfloat16, wmma::row_major> fPl;
                wmma::load_matrix_sync(fPh, &Ph[wr * 16][ks * 16], PP);
                wmma::load_matrix_sync(fPl, &Pl[wr * 16][ks * 16], PP);
#pragma unroll
                for (int nj = 0; nj < 2; nj++) {
                    wmma::fragment<wmma::matrix_b, 16, 16, 16, __nv_bfloat16, wmma::row_major> fVh;
                    wmma::fragment<wmma::matrix_b, 16, 16, 16, __nv_bfloat16, wmma::row_major> fVl;
                    wmma::load_matrix_sync(fVh, &Vh[ks * 16][wc * 32 + nj * 16], KP);
                    wmma::load_matrix_sync(fVl, &Vl[ks * 16][wc * 32 + nj * 16], KP);
                    wmma::mma_sync(accO[nj], fPh, fVh, accO[nj]);
                    wmma::mma_sync(accO[nj], fPh, fVl, accO[nj]);
                    wmma::mma_sync(accO[nj], fPl, fVh, accO[nj]);
                }
            }
            // S region is dead (softmax consumed it before b3) -> safe to store O
            wmma::store_matrix_sync(&SsOs[wr * 16][wc * 32],      accO[0], OP, wmma::mem_row_major);
            wmma::store_matrix_sync(&SsOs[wr * 16][wc * 32 + 16], accO[1], OP, wmma::mem_row_major);
        }
        __syncthreads();   // b4

        // ---- rescale + accumulate into register O ------------------------------
#pragma unroll
        for (int i = 0; i < 4; i++) {
            const float cr = corr_s[qr0 + i];
#pragma unroll
            for (int j = 0; j < 4; j++) {
                o[i][j] = o[i][j] * cr + SsOs[qr0 + i][dc0 + j];
            }
        }
        // no end barrier: next iteration writes Kh/Vh (disjoint from SsOs),
        // and next write to SsOs (S store) is after b1+b2.
    }

    // ---- normalize and write ctx[b][t][h*DH + d] -----------------------------
#pragma unroll
    for (int i = 0; i < 4; i++) {
        const float inv = 1.f / l_s[qr0 + i];
        const size_t off =
            (size_t)(b * Tc + qt * BQ + qr0 + i) * Dc + h * DHc + dc0;
        *reinterpret_cast<float4*>(g_ctx + off) =
            make_float4(o[i][0] * inv, o[i][1] * inv, o[i][2] * inv, o[i][3] * inv);
    }
}

// ---------------- launch ------------------------------------------------------
extern "C" void kernel_launch(void* const* d_in, const int* in_sizes, int n_in,
                              void* d_out, int out_size) {
    const float* x  = (const float*)d_in[0];
    const float* Wq = (const float*)d_in[1];
    const float* Wk = (const float*)d_in[2];
    const float* Wv = (const float*)d_in[3];
    const float* Wo = (const float*)d_in[4];
    float* out = (float*)d_out;

    dim3 gridBig(Dc / 128, BT / 128);
    dim3 gridKV(DKV / 128, BT / 128);

    k_qproj<<<gridBig, 256>>>(x, Wq);
    k_kproj<<<gridKV, 256>>>(x, Wk);
    k_vproj<<<gridKV, 256>>>(x, Wv);

    rope_q_kernel<<<(BT * Dc) / 256, 256>>>();
    rope_k_kernel<<<(BT * DKV) / 256, 256>>>();

    attn_kernel<<<dim3(Tc / 64, Hc, Bc), 256>>>();

    k_oproj<<<gridBig, 256>>>(Wo, out);
}

// round 9
// speedup vs baseline: 1.6072x; 1.0346x over previous
#include <cuda_runtime.h>
#include <cuda_bf16.h>
#include <mma.h>
#include <math.h>

using namespace nvcuda;

// Problem constants
constexpr int Bc   = 2;
constexpr int Tc   = 2048;
constexpr int Dc   = 2048;
constexpr int Hc   = 32;
constexpr int HKVc = 8;
constexpr int DHc  = 64;
constexpr int BT   = Bc * Tc;          // 4096
constexpr int DKV  = HKVc * DHc;       // 512

// ---------------- scratch (__device__ globals, no allocation) ----------------
// NOTE: only ever referenced from DEVICE code (never passed from host).
__device__ float g_qraw[BT * Dc];
__device__ float g_kraw[BT * DKV];
__device__ float g_vraw[BT * DKV];
__device__ float g_ctx [BT * Dc];

// pre-split bf16 hi/lo operand buffers
__device__ __nv_bfloat16 g_xh [BT * Dc],  g_xl [BT * Dc];
__device__ __nv_bfloat16 g_wqh[Dc * Dc],  g_wql[Dc * Dc];
__device__ __nv_bfloat16 g_wkh[Dc * DKV], g_wkl[Dc * DKV];
__device__ __nv_bfloat16 g_wvh[Dc * DKV], g_wvl[Dc * DKV];
__device__ __nv_bfloat16 g_woh[Dc * Dc],  g_wol[Dc * Dc];
__device__ __nv_bfloat16 g_qh [BT * Dc],  g_ql [BT * Dc];   // [B,H,T,DH] roped
__device__ __nv_bfloat16 g_kh [BT * DKV], g_kl [BT * DKV];  // [B,HKV,T,DH] roped
__device__ __nv_bfloat16 g_vh [BT * DKV], g_vl [BT * DKV];  // [B,HKV,T,DH]
__device__ __nv_bfloat16 g_ctxh[BT * Dc], g_ctxl[BT * Dc];

// ---------------- helpers -----------------------------------------------------
__device__ __forceinline__ void split4(const float4 v,
                                       __nv_bfloat16* hi, __nv_bfloat16* lo) {
    const __nv_bfloat16 hx = __float2bfloat16_rn(v.x);
    const __nv_bfloat16 hy = __float2bfloat16_rn(v.y);
    const __nv_bfloat16 hz = __float2bfloat16_rn(v.z);
    const __nv_bfloat16 hw = __float2bfloat16_rn(v.w);
    __nv_bfloat162* h2 = reinterpret_cast<__nv_bfloat162*>(hi);
    __nv_bfloat162* l2 = reinterpret_cast<__nv_bfloat162*>(lo);
    h2[0] = __halves2bfloat162(hx, hy);
    h2[1] = __halves2bfloat162(hz, hw);
    l2[0] = __halves2bfloat162(__float2bfloat16_rn(v.x - __bfloat162float(hx)),
                               __float2bfloat16_rn(v.y - __bfloat162float(hy)));
    l2[1] = __halves2bfloat162(__float2bfloat16_rn(v.z - __bfloat162float(hz)),
                               __float2bfloat16_rn(v.w - __bfloat162float(hw)));
}

// ---------------- elementwise split kernels -----------------------------------
__global__ __launch_bounds__(256) void k_split_x(const float* __restrict__ src) {
    const int i = blockIdx.x * 256 + threadIdx.x;
    const float4 v = reinterpret_cast<const float4*>(src)[i];
    split4(v, g_xh + (size_t)i * 4, g_xl + (size_t)i * 4);
}
__global__ __launch_bounds__(256) void k_split_wq(const float* __restrict__ src) {
    const int i = blockIdx.x * 256 + threadIdx.x;
    const float4 v = reinterpret_cast<const float4*>(src)[i];
    split4(v, g_wqh + (size_t)i * 4, g_wql + (size_t)i * 4);
}
__global__ __launch_bounds__(256) void k_split_wk(const float* __restrict__ src) {
    const int i = blockIdx.x * 256 + threadIdx.x;
    const float4 v = reinterpret_cast<const float4*>(src)[i];
    split4(v, g_wkh + (size_t)i * 4, g_wkl + (size_t)i * 4);
}
__global__ __launch_bounds__(256) void k_split_wv(const float* __restrict__ src) {
    const int i = blockIdx.x * 256 + threadIdx.x;
    const float4 v = reinterpret_cast<const float4*>(src)[i];
    split4(v, g_wvh + (size_t)i * 4, g_wvl + (size_t)i * 4);
}
__global__ __launch_bounds__(256) void k_split_wo(const float* __restrict__ src) {
    const int i = blockIdx.x * 256 + threadIdx.x;
    const float4 v = reinterpret_cast<const float4*>(src)[i];
    split4(v, g_woh + (size_t)i * 4, g_wol + (size_t)i * 4);
}
__global__ __launch_bounds__(256) void k_split_ctx() {
    const int i = blockIdx.x * 256 + threadIdx.x;
    const float4 v = reinterpret_cast<const float4*>(g_ctx)[i];
    split4(v, g_ctxh + (size_t)i * 4, g_ctxl + (size_t)i * 4);
}
// V: [B,T,HKV*DH] -> [B,HKV,T,DH], split to hi/lo
__global__ __launch_bounds__(256) void k_split_v() {
    const int i4 = blockIdx.x * 256 + threadIdx.x;   // over BT*DKV/4
    const int e  = i4 * 4;
    const int d  = e & 63;
    const int t  = (e >> 6) & 2047;
    const int kv = (e >> 17) & 7;
    const int b  = e >> 20;
    const float4 v = *reinterpret_cast<const float4*>(
        g_vraw + (size_t)(b * Tc + t) * DKV + kv * DHc + d);
    split4(v, g_vh + e, g_vl + e);
}

// ---------------- pure bf16 GEMM via wmma (device body) ----------------------
// C[4096, N] = (Ah+Al)[4096, 2048] @ (Bh+Bl)[2048, N]  (bf16x3: drops Al*Bl)
// block = 256 (8 warps: 4 along M x 2 along N), CTA tile 128x128, BK=32.
template <int N>
__device__ __forceinline__ void bf16_gemm_body(const __nv_bfloat16* __restrict__ Ahg,
                                               const __nv_bfloat16* __restrict__ Alg,
                                               const __nv_bfloat16* __restrict__ Bhg,
                                               const __nv_bfloat16* __restrict__ Blg,
                                               float* __restrict__ C) {
    constexpr int K  = 2048;
    constexpr int BM = 128, BN = 128, BK = 32;
    constexpr int ASTR = BK + 8;   // 40 bf16 = 80 B per row
    constexpr int BSTR = BN + 8;   // 136 bf16 = 272 B per row

    __shared__ __align__(32) __nv_bfloat16 Ah[BM][ASTR];
    __shared__ __align__(32) __nv_bfloat16 Al[BM][ASTR];
    __shared__ __align__(32) __nv_bfloat16 Bh[BK][BSTR];
    __shared__ __align__(32) __nv_bfloat16 Bl[BK][BSTR];

    const int tid  = threadIdx.x;
    const int warp = tid >> 5;
    const int wm   = (warp >> 1) * 32;
    const int wn   = (warp & 1) * 64;
    const int brow = blockIdx.y * BM;
    const int bcol = blockIdx.x * BN;

    // A tile: 128x32 bf16 = 512 uint4 per array; 2 per thread
    const int ar0 = tid >> 2;              // row of first A vec (0..63)
    const int ac  = (tid & 3) * 8;         // col (bf16 units)
    // B tile: 32x128 bf16 = 512 uint4 per array; 2 per thread
    const int br0 = tid >> 4;              // row of first B vec (0..15)
    const int bc  = (tid & 15) * 8;

    wmma::fragment<wmma::accumulator, 16, 16, 16, float> acc[2][4];
#pragma unroll
    for (int mi = 0; mi < 2; mi++) {
#pragma unroll
        for (int nj = 0; nj < 4; nj++) {
            wmma::fill_fragment(acc[mi][nj], 0.0f);
        }
    }

    uint4 ahR[2], alR[2], bhR[2], blR[2];
#pragma unroll
    for (int j = 0; j < 2; j++) {
        const size_t aoff = (size_t)(brow + ar0 + j * 64) * K + ac;
        ahR[j] = *reinterpret_cast<const uint4*>(Ahg + aoff);
        alR[j] = *reinterpret_cast<const uint4*>(Alg + aoff);
        const size_t boff = (size_t)(br0 + j * 16) * N + bcol + bc;
        bhR[j] = *reinterpret_cast<const uint4*>(Bhg + boff);
        blR[j] = *reinterpret_cast<const uint4*>(Blg + boff);
    }

    for (int kt = 0; kt < K / BK; kt++) {
#pragma unroll
        for (int j = 0; j < 2; j++) {
            *reinterpret_cast<uint4*>(&Ah[ar0 + j * 64][ac]) = ahR[j];
            *reinterpret_cast<uint4*>(&Al[ar0 + j * 64][ac]) = alR[j];
            *reinterpret_cast<uint4*>(&Bh[br0 + j * 16][bc]) = bhR[j];
            *reinterpret_cast<uint4*>(&Bl[br0 + j * 16][bc]) = blR[j];
        }
        __syncthreads();

        if (kt + 1 < K / BK) {
            const int k0 = (kt + 1) * BK;
#pragma unroll
            for (int j = 0; j < 2; j++) {
                const size_t aoff = (size_t)(brow + ar0 + j * 64) * K + k0 + ac;
                ahR[j] = *reinterpret_cast<const uint4*>(Ahg + aoff);
                alR[j] = *reinterpret_cast<const uint4*>(Alg + aoff);
                const size_t boff = (size_t)(k0 + br0 + j * 16) * N + bcol + bc;
                bhR[j] = *reinterpret_cast<const uint4*>(Bhg + boff);
                blR[j] = *reinterpret_cast<const uint4*>(Blg + boff);
            }
        }

#pragma unroll
        for (int ks = 0; ks < 2; ks++) {
            wmma::fragment<wmma::matrix_a, 16, 16, 16, __nv_bfloat16, wmma::row_major> fAh[2];
            wmma::fragment<wmma::matrix_a, 16, 16, 16, __nv_bfloat16, wmma::row_major> fAl[2];
#pragma unroll
            for (int mi = 0; mi < 2; mi++) {
                wmma::load_matrix_sync(fAh[mi], &Ah[wm + mi * 16][ks * 16], ASTR);
                wmma::load_matrix_sync(fAl[mi], &Al[wm + mi * 16][ks * 16], ASTR);
            }
#pragma unroll
            for (int nj = 0; nj < 4; nj++) {
                wmma::fragment<wmma::matrix_b, 16, 16, 16, __nv_bfloat16, wmma::row_major> fBh;
                wmma::fragment<wmma::matrix_b, 16, 16, 16, __nv_bfloat16, wmma::row_major> fBl;
                wmma::load_matrix_sync(fBh, &Bh[ks * 16][wn + nj * 16], BSTR);
                wmma::load_matrix_sync(fBl, &Bl[ks * 16][wn + nj * 16], BSTR);
#pragma unroll
                for (int mi = 0; mi < 2; mi++) {
                    wmma::mma_sync(acc[mi][nj], fAh[mi], fBh, acc[mi][nj]);
                    wmma::mma_sync(acc[mi][nj], fAh[mi], fBl, acc[mi][nj]);
                    wmma::mma_sync(acc[mi][nj], fAl[mi], fBh, acc[mi][nj]);
                }
            }
        }
        __syncthreads();
    }

#pragma unroll
    for (int mi = 0; mi < 2; mi++) {
#pragma unroll
        for (int nj = 0; nj < 4; nj++) {
            float* p = C + (size_t)(brow + wm + mi * 16) * N + bcol + wn + nj * 16;
            wmma::store_matrix_sync(p, acc[mi][nj], N, wmma::mem_row_major);
        }
    }
}

// Wrappers: scratch globals referenced from DEVICE code only.
__global__ __launch_bounds__(256) void k_qproj() {
    bf16_gemm_body<Dc>(g_xh, g_xl, g_wqh, g_wql, g_qraw);
}
__global__ __launch_bounds__(256) void k_kproj() {
    bf16_gemm_body<DKV>(g_xh, g_xl, g_wkh, g_wkl, g_kraw);
}
__global__ __launch_bounds__(256) void k_vproj() {
    bf16_gemm_body<DKV>(g_xh, g_xl, g_wvh, g_wvl, g_vraw);
}
__global__ __launch_bounds__(256) void k_oproj(float* __restrict__ out) {
    bf16_gemm_body<Dc>(g_ctxh, g_ctxl, g_woh, g_wol, out);
}

// ---------------- RoPE (fused hi/lo split output) -----------------------------
#define ROPE_LN_C 0.28782313662425575f

__global__ __launch_bounds__(256) void rope_q_kernel() {
    const int idx = blockIdx.x * 256 + threadIdx.x;   // over [B,H,T,DH]
    const int d = idx & 63;
    const int t = (idx >> 6) & 2047;
    const int h = (idx >> 17) & 31;
    const int b = idx >> 22;
    const size_t row = (size_t)(b * Tc + t) * Dc + h * DHc;
    const float raw  = g_qraw[row + d];
    const float pair = g_qraw[row + ((d < 32) ? d + 32 : d - 32)];
    const float rot  = (d < 32) ? -pair : pair;
    const int   i    = d & 31;
    const float invf = expf(-(float)i * ROPE_LN_C);
    const float ang  = (float)t * invf;
    const float val  = raw * cosf(ang) + rot * sinf(ang);
    const __nv_bfloat16 hi = __float2bfloat16_rn(val);
    g_qh[idx] = hi;
    g_ql[idx] = __float2bfloat16_rn(val - __bfloat162float(hi));
}

__global__ __launch_bounds__(256) void rope_k_kernel() {
    const int idx = blockIdx.x * 256 + threadIdx.x;   // over [B,HKV,T,DH]
    const int d  = idx & 63;
    const int t  = (idx >> 6) & 2047;
    const int kv = (idx >> 17) & 7;
    const int b  = idx >> 20;
    const size_t row = (size_t)(b * Tc + t) * DKV + kv * DHc;
    const float raw  = g_kraw[row + d];
    const float pair = g_kraw[row + ((d < 32) ? d + 32 : d - 32)];
    const float rot  = (d < 32) ? -pair : pair;
    const int   i    = d & 31;
    const float invf = expf(-(float)i * ROPE_LN_C);
    const float ang  = (float)t * invf;
    const float val  = raw * cosf(ang) + rot * sinf(ang);
    const __nv_bfloat16 hi = __float2bfloat16_rn(val);
    g_kh[idx] = hi;
    g_kl[idx] = __float2bfloat16_rn(val - __bfloat162float(hi));
}

// ---------------- Causal flash attention (bf16x3 wmma, parallel softmax) -----
// grid: (T/64, H, B), block: 256 (8 warps: 4 along q x 2 along key/dh)
__global__ __launch_bounds__(256) void attn_kernel() {
    constexpr int BQ  = 64;
    constexpr int BKT = 32;
    constexpr int KP  = 72;   // bf16 row stride for K/V/Q-staging
    constexpr int PP  = 40;   // bf16 row stride for P
    constexpr int OP  = 72;   // fp32 row stride for Ss/Os

    __shared__ __align__(32) __nv_bfloat16 Kh[BKT][KP];
    __shared__ __align__(32) __nv_bfloat16 Kl[BKT][KP];
    __shared__ __align__(32) __nv_bfloat16 Vh[BKT][KP];
    __shared__ __align__(32) __nv_bfloat16 Vl[BKT][KP];
    __shared__ __align__(32) __nv_bfloat16 Ph[BQ][PP];
    __shared__ __align__(32) __nv_bfloat16 Pl[BQ][PP];
    __shared__ __align__(32) float SsOs[BQ][OP];   // Q staging, S tile, O tile
    __shared__ float m_s[BQ], l_s[BQ], corr_s[BQ];

    const int tid  = threadIdx.x;
    const int warp = tid >> 5;
    const int wr   = warp >> 1;    // 0..3: 16-row group of q
    const int wc   = warp & 1;     // 0..1: 16-col group (S) / 32-col group (O)
    const int qt   = blockIdx.x;
    const int h    = blockIdx.y;
    const int b    = blockIdx.z;
    const int kv   = h >> 2;

    const size_t qoff = ((size_t)(b * Hc + h) * Tc + qt * BQ) * DHc;
    const size_t koff = (size_t)(b * HKVc + kv) * Tc * DHc;

    // ---- stage Q hi/lo (bf16) into SsOs region, then load fragments ----------
    __nv_bfloat16* Qhs = reinterpret_cast<__nv_bfloat16*>(&SsOs[0][0]);
    __nv_bfloat16* Qls = Qhs + BQ * KP;
#pragma unroll
    for (int j = 0; j < 2; j++) {
        const int i = tid + j * 256;            // 512 uint4 total (64x64 bf16)
        const int r = i >> 3;
        const int c = (i & 7) * 8;
        *reinterpret_cast<uint4*>(Qhs + r * KP + c) =
            *reinterpret_cast<const uint4*>(g_qh + qoff + (size_t)r * DHc + c);
        *reinterpret_cast<uint4*>(Qls + r * KP + c) =
            *reinterpret_cast<const uint4*>(g_ql + qoff + (size_t)r * DHc + c);
    }
    if (tid < BQ) { m_s[tid] = -1e30f; l_s[tid] = 0.f; }
    __syncthreads();

    wmma::fragment<wmma::matrix_a, 16, 16, 16, __nv_bfloat16, wmma::row_major> fQh[4];
    wmma::fragment<wmma::matrix_a, 16, 16, 16, __nv_bfloat16, wmma::row_major> fQl[4];
#pragma unroll
    for (int kd = 0; kd < 4; kd++) {
        wmma::load_matrix_sync(fQh[kd], Qhs + (wr * 16) * KP + kd * 16, KP);
        wmma::load_matrix_sync(fQl[kd], Qls + (wr * 16) * KP + kd * 16, KP);
    }
    __syncthreads();   // Q staging region is reused as S/O below

    float o[4][4];
#pragma unroll
    for (int i = 0; i < 4; i++) {
#pragma unroll
        for (int j = 0; j < 4; j++) { o[i][j] = 0.f; }
    }
    const int qr0  = (tid >> 4) * 4;   // output rows
    const int dc0  = (tid & 15) * 4;   // output cols
    const int srow = tid >> 2;         // softmax row (4 threads per row)
    const int ssub = tid & 3;          // softmax sub-column group (8 cols)
    const int ntiles = 2 * qt + 2;

    // K/V tile loads: 32x64 bf16 = 256 uint4 per array, 1 per thread
    const int lr = tid >> 3;           // 0..31
    const int lc = (tid & 7) * 8;      // 0..56

    uint4 kRegH, kRegL, vRegH, vRegL;
    {
        const size_t off = koff + (size_t)lr * DHc + lc;
        kRegH = *reinterpret_cast<const uint4*>(g_kh + off);
        kRegL = *reinterpret_cast<const uint4*>(g_kl + off);
        vRegH = *reinterpret_cast<const uint4*>(g_vh + off);
        vRegL = *reinterpret_cast<const uint4*>(g_vl + off);
    }

    for (int kt = 0; kt < ntiles; kt++) {
        const int kbase = kt * BKT;

        // ---- store current K/V tile --------------------------------------------
        *reinterpret_cast<uint4*>(&Kh[lr][lc]) = kRegH;
        *reinterpret_cast<uint4*>(&Kl[lr][lc]) = kRegL;
        *reinterpret_cast<uint4*>(&Vh[lr][lc]) = vRegH;
        *reinterpret_cast<uint4*>(&Vl[lr][lc]) = vRegL;
        __syncthreads();   // b1

        // ---- prefetch next tile ------------------------------------------------
        if (kt + 1 < ntiles) {
            const size_t off = koff + (size_t)(kbase + BKT + lr) * DHc + lc;
            kRegH = *reinterpret_cast<const uint4*>(g_kh + off);
            kRegL = *reinterpret_cast<const uint4*>(g_kl + off);
            vRegH = *reinterpret_cast<const uint4*>(g_vh + off);
            vRegL = *reinterpret_cast<const uint4*>(g_vl + off);
        }

        // ---- S = Q K^T (bf16x3), each warp a 16x16 block -----------------------
        {
            wmma::fragment<wmma::accumulator, 16, 16, 16, float> accS;
            wmma::fill_fragment(accS, 0.0f);
#pragma unroll
            for (int kd = 0; kd < 4; kd++) {
                wmma::fragment<wmma::matrix_b, 16, 16, 16, __nv_bfloat16, wmma::col_major> fKh;
                wmma::fragment<wmma::matrix_b, 16, 16, 16, __nv_bfloat16, wmma::col_major> fKl;
                wmma::load_matrix_sync(fKh, &Kh[wc * 16][kd * 16], KP);
                wmma::load_matrix_sync(fKl, &Kl[wc * 16][kd * 16], KP);
                wmma::mma_sync(accS, fQh[kd], fKh, accS);
                wmma::mma_sync(accS, fQh[kd], fKl, accS);
                wmma::mma_sync(accS, fQl[kd], fKh, accS);
            }
            wmma::store_matrix_sync(&SsOs[wr * 16][wc * 16], accS, OP, wmma::mem_row_major);
        }
        __syncthreads();   // b2

        // ---- online softmax: 4 threads per row, 8 cols each --------------------
        {
            const int qi = qt * BQ + srow;
            const float mold = m_s[srow];
            float sv[8];
            float mmax = mold;
#pragma unroll
            for (int j = 0; j < 8; j++) {
                const int ccol = ssub * 8 + j;
                const float s = (kbase + ccol <= qi) ? SsOs[srow][ccol] * 0.125f : -1e30f;
                sv[j] = s;
                mmax = fmaxf(mmax, s);
            }
            mmax = fmaxf(mmax, __shfl_xor_sync(0xffffffffu, mmax, 1));
            mmax = fmaxf(mmax, __shfl_xor_sync(0xffffffffu, mmax, 2));
            float lsum = 0.f;
#pragma unroll
            for (int j = 0; j < 8; j++) {
                const float e = __expf(sv[j] - mmax);
                lsum += e;
                const __nv_bfloat16 eh = __float2bfloat16_rn(e);
                Ph[srow][ssub * 8 + j] = eh;
                Pl[srow][ssub * 8 + j] = __float2bfloat16_rn(e - __bfloat162float(eh));
            }
            lsum += __shfl_xor_sync(0xffffffffu, lsum, 1);
            lsum += __shfl_xor_sync(0xffffffffu, lsum, 2);
            if (ssub == 0) {
                const float cr = __expf(mold - mmax);
                m_s[srow]    = mmax;
                l_s[srow]    = l_s[srow] * cr + lsum;
                corr_s[srow] = cr;
            }
        }
        __syncthreads();   // b3

        // ---- O_tile = P V (bf16x3), each warp 16x32 ----------------------------
        {
            wmma::fragment<wmma::accumulator, 16, 16, 16, float> accO[2];
            wmma::fill_fragment(accO[0], 0.0f);
            wmma::fill_fragment(accO[1], 0.0f);
#pragma unroll
            for (int ks = 0; ks < 2; ks++) {
                wmma::fragment<wmma::matrix_a, 16, 16, 16, __nv_bfloat16, wmma::row_major> fPh;
                wmma::fragment<wmma::matrix_a, 16, 16, 16, __nv_bfloat16, wmma::row_major> fPl;
                wmma::load_matrix_sync(fPh, &Ph[wr * 16][ks * 16], PP);
                wmma::load_matrix_sync(fPl, &Pl[wr * 16][ks * 16], PP);
#pragma unroll
                for (int nj = 0; nj < 2; nj++) {
                    wmma::fragment<wmma::matrix_b, 16, 16, 16, __nv_bfloat16, wmma::row_major> fVh;
                    wmma::fragment<wmma::matrix_b, 16, 16, 16, __nv_bfloat16, wmma::row_major> fVl;
                    wmma::load_matrix_sync(fVh, &Vh[ks * 16][wc * 32 + nj * 16], KP);
                    wmma::load_matrix_sync(fVl, &Vl[ks * 16][wc * 32 + nj * 16], KP);
                    wmma::mma_sync(accO[nj], fPh, fVh, accO[nj]);
                    wmma::mma_sync(accO[nj], fPh, fVl, accO[nj]);
                    wmma::mma_sync(accO[nj], fPl, fVh, accO[nj]);
                }
            }
            wmma::store_matrix_sync(&SsOs[wr * 16][wc * 32],      accO[0], OP, wmma::mem_row_major);
            wmma::store_matrix_sync(&SsOs[wr * 16][wc * 32 + 16], accO[1], OP, wmma::mem_row_major);
        }
        __syncthreads();   // b4

        // ---- rescale + accumulate into register O ------------------------------
#pragma unroll
        for (int i = 0; i < 4; i++) {
            const float cr = corr_s[qr0 + i];
#pragma unroll
            for (int j = 0; j < 4; j++) {
                o[i][j] = o[i][j] * cr + SsOs[qr0 + i][dc0 + j];
            }
        }
        // no end barrier: next iteration writes Kh/Vh (disjoint from SsOs),
        // and next write to SsOs (S store) is after b1+b2.
    }

    // ---- normalize and write ctx[b][t][h*DH + d] -----------------------------
#pragma unroll
    for (int i = 0; i < 4; i++) {
        const float inv = 1.f / l_s[qr0 + i];
        const size_t off =
            (size_t)(b * Tc + qt * BQ + qr0 + i) * Dc + h * DHc + dc0;
        *reinterpret_cast<float4*>(g_ctx + off) =
            make_float4(o[i][0] * inv, o[i][1] * inv, o[i][2] * inv, o[i][3] * inv);
    }
}

// ---------------- launch ------------------------------------------------------
extern "C" void kernel_launch(void* const* d_in, const int* in_sizes, int n_in,
                              void* d_out, int out_size) {
    const float* x  = (const float*)d_in[0];
    const float* Wq = (const float*)d_in[1];
    const float* Wk = (const float*)d_in[2];
    const float* Wv = (const float*)d_in[3];
    const float* Wo = (const float*)d_in[4];
    float* out = (float*)d_out;

    // pre-split inputs and weights to bf16 hi/lo
    k_split_x <<<(BT * Dc)  / 1024, 256>>>(x);
    k_split_wq<<<(Dc * Dc)  / 1024, 256>>>(Wq);
    k_split_wk<<<(Dc * DKV) / 1024, 256>>>(Wk);
    k_split_wv<<<(Dc * DKV) / 1024, 256>>>(Wv);
    k_split_wo<<<(Dc * Dc)  / 1024, 256>>>(Wo);

    dim3 gridBig(Dc / 128, BT / 128);
    dim3 gridKV(DKV / 128, BT / 128);

    k_qproj<<<gridBig, 256>>>();
    k_kproj<<<gridKV, 256>>>();
    k_vproj<<<gridKV, 256>>>();

    rope_q_kernel<<<(BT * Dc) / 256, 256>>>();
    rope_k_kernel<<<(BT * DKV) / 256, 256>>>();
    k_split_v<<<(BT * DKV) / 1024, 256>>>();

    attn_kernel<<<dim3(Tc / 64, Hc, Bc), 256>>>();

    k_split_ctx<<<(BT * Dc) / 1024, 256>>>();
    k_oproj<<<gridBig, 256>>>(out);
}